// round 1
// baseline (speedup 1.0000x reference)
#include <cuda_runtime.h>

#define N_NODES 100000
#define N_EDGES 1600000
#define D       128
#define LN_EPS  1e-5f

#define SCAN_BLK 512
#define NB_SCAN  ((N_NODES + SCAN_BLK - 1) / SCAN_BLK)   // 196

// ------- scratch (device globals; no allocation allowed) -------
__device__ int   g_rowptr[N_NODES + 1];
__device__ int   g_cursor[N_NODES];
__device__ int   g_partials[256];
__device__ int   g_ssrc[N_EDGES];
__device__ float g_sval[N_EDGES];
__device__ float g_h[N_NODES * D];        // intermediate activations (51.2 MB)

// ---------------------------------------------------------------
// CSR build
// ---------------------------------------------------------------
__global__ void k_zero() {
    int i = blockIdx.x * blockDim.x + threadIdx.x;
    int stride = gridDim.x * blockDim.x;
    for (int j = i; j <= N_NODES; j += stride) g_rowptr[j] = 0;
    for (int j = i; j <  N_NODES; j += stride) g_cursor[j] = 0;
}

__global__ void k_hist(const int* __restrict__ dst) {
    int e = blockIdx.x * blockDim.x + threadIdx.x;
    if (e < N_EDGES) atomicAdd(&g_rowptr[dst[e] + 1], 1);
}

// inclusive scan within blocks of 512 counts; block sums to g_partials
__global__ void k_scan1() {
    __shared__ int sh[SCAN_BLK];
    int t = threadIdx.x;
    int i = blockIdx.x * SCAN_BLK + t;          // count index in [0, N)
    int v = (i < N_NODES) ? g_rowptr[i + 1] : 0;
    sh[t] = v;
    __syncthreads();
    #pragma unroll
    for (int off = 1; off < SCAN_BLK; off <<= 1) {
        int a = (t >= off) ? sh[t - off] : 0;
        __syncthreads();
        sh[t] += a;
        __syncthreads();
    }
    if (i < N_NODES) g_rowptr[i + 1] = sh[t];
    if (t == SCAN_BLK - 1) g_partials[blockIdx.x] = sh[t];
}

// single-block exclusive scan of the 196 block sums
__global__ void k_scan2() {
    __shared__ int sh[256];
    int t = threadIdx.x;                         // 256 threads
    int v = (t < NB_SCAN) ? g_partials[t] : 0;
    sh[t] = v;
    __syncthreads();
    #pragma unroll
    for (int off = 1; off < 256; off <<= 1) {
        int a = (t >= off) ? sh[t - off] : 0;
        __syncthreads();
        sh[t] += a;
        __syncthreads();
    }
    if (t < NB_SCAN) g_partials[t] = sh[t] - v;  // exclusive
}

__global__ void k_addback() {
    int i = blockIdx.x * blockDim.x + threadIdx.x;
    if (i < N_NODES) g_rowptr[i + 1] += g_partials[i >> 9];  // 512 per scan block
}

__global__ void k_scatter(const int* __restrict__ src,
                          const int* __restrict__ dst,
                          const float* __restrict__ val) {
    int e = blockIdx.x * blockDim.x + threadIdx.x;
    if (e >= N_EDGES) return;
    int d = dst[e];
    int p = g_rowptr[d] + atomicAdd(&g_cursor[d], 1);
    g_ssrc[p] = src[e];
    g_sval[p] = val[e];
}

// ---------------------------------------------------------------
// fused gather-aggregate + diag-scale + LayerNorm (+ReLU)
// one warp per node; lane l owns features [4l, 4l+4)
// ---------------------------------------------------------------
template <bool RELU>
__device__ __forceinline__ void agg_node(const float* __restrict__ in,
                                         const float* __restrict__ w,
                                         const float* __restrict__ gam,
                                         const float* __restrict__ bet,
                                         float* __restrict__ out) {
    int warp = (blockIdx.x * blockDim.x + threadIdx.x) >> 5;
    int lane = threadIdx.x & 31;
    if (warp >= N_NODES) return;

    int beg = g_rowptr[warp];
    int end = g_rowptr[warp + 1];

    float4 acc = make_float4(0.f, 0.f, 0.f, 0.f);
    const float4* in4 = (const float4*)in;

    int e = beg;
    // unroll-by-4: 4 independent row loads in flight per warp
    for (; e + 4 <= end; e += 4) {
        int   s0 = g_ssrc[e],     s1 = g_ssrc[e + 1];
        int   s2 = g_ssrc[e + 2], s3 = g_ssrc[e + 3];
        float v0 = g_sval[e],     v1 = g_sval[e + 1];
        float v2 = g_sval[e + 2], v3 = g_sval[e + 3];
        float4 x0 = in4[s0 * 32 + lane];
        float4 x1 = in4[s1 * 32 + lane];
        float4 x2 = in4[s2 * 32 + lane];
        float4 x3 = in4[s3 * 32 + lane];
        acc.x = fmaf(v0, x0.x, acc.x); acc.y = fmaf(v0, x0.y, acc.y);
        acc.z = fmaf(v0, x0.z, acc.z); acc.w = fmaf(v0, x0.w, acc.w);
        acc.x = fmaf(v1, x1.x, acc.x); acc.y = fmaf(v1, x1.y, acc.y);
        acc.z = fmaf(v1, x1.z, acc.z); acc.w = fmaf(v1, x1.w, acc.w);
        acc.x = fmaf(v2, x2.x, acc.x); acc.y = fmaf(v2, x2.y, acc.y);
        acc.z = fmaf(v2, x2.z, acc.z); acc.w = fmaf(v2, x2.w, acc.w);
        acc.x = fmaf(v3, x3.x, acc.x); acc.y = fmaf(v3, x3.y, acc.y);
        acc.z = fmaf(v3, x3.z, acc.z); acc.w = fmaf(v3, x3.w, acc.w);
    }
    for (; e < end; e++) {
        int   s = g_ssrc[e];
        float v = g_sval[e];
        float4 x0 = in4[s * 32 + lane];
        acc.x = fmaf(v, x0.x, acc.x); acc.y = fmaf(v, x0.y, acc.y);
        acc.z = fmaf(v, x0.z, acc.z); acc.w = fmaf(v, x0.w, acc.w);
    }

    // diag transform folded in after aggregation: t = acc * w
    float4 w4 = ((const float4*)w)[lane];
    float4 t;
    t.x = acc.x * w4.x; t.y = acc.y * w4.y;
    t.z = acc.z * w4.z; t.w = acc.w * w4.w;

    // LayerNorm across 128 features via warp reduce
    float s  = t.x + t.y + t.z + t.w;
    float sq = t.x * t.x + t.y * t.y + t.z * t.z + t.w * t.w;
    #pragma unroll
    for (int o = 16; o; o >>= 1) {
        s  += __shfl_xor_sync(0xffffffffu, s,  o);
        sq += __shfl_xor_sync(0xffffffffu, sq, o);
    }
    float mu  = s * (1.f / D);
    float var = sq * (1.f / D) - mu * mu;
    float rs  = rsqrtf(var + LN_EPS);

    float4 g4 = ((const float4*)gam)[lane];
    float4 b4 = ((const float4*)bet)[lane];
    float4 o4;
    o4.x = fmaf((t.x - mu) * rs, g4.x, b4.x);
    o4.y = fmaf((t.y - mu) * rs, g4.y, b4.y);
    o4.z = fmaf((t.z - mu) * rs, g4.z, b4.z);
    o4.w = fmaf((t.w - mu) * rs, g4.w, b4.w);
    if (RELU) {
        o4.x = fmaxf(o4.x, 0.f); o4.y = fmaxf(o4.y, 0.f);
        o4.z = fmaxf(o4.z, 0.f); o4.w = fmaxf(o4.w, 0.f);
    }
    ((float4*)out)[warp * 32 + lane] = o4;
}

__global__ void k_layer0(const float* __restrict__ x,
                         const float* __restrict__ w,
                         const float* __restrict__ gam,
                         const float* __restrict__ bet) {
    agg_node<true>(x, w, gam, bet, g_h);
}

__global__ void k_layer1(const float* __restrict__ w,
                         const float* __restrict__ gam,
                         const float* __restrict__ bet,
                         float* __restrict__ out) {
    agg_node<false>(g_h, w, gam, bet, out);
}

// ---------------------------------------------------------------
extern "C" void kernel_launch(void* const* d_in, const int* in_sizes, int n_in,
                              void* d_out, int out_size) {
    const float* x     = (const float*)d_in[0];
    const int*   esrc  = (const int*)  d_in[1];
    const int*   edst  = (const int*)  d_in[2];
    const float* eval_ = (const float*)d_in[3];
    const float* w1    = (const float*)d_in[4];
    const float* w2    = (const float*)d_in[5];
    const float* ln1g  = (const float*)d_in[6];
    const float* ln1b  = (const float*)d_in[7];
    const float* ln2g  = (const float*)d_in[8];
    const float* ln2b  = (const float*)d_in[9];
    float* out = (float*)d_out;

    // CSR build (per call; deterministic work)
    k_zero<<<256, 256>>>();
    k_hist<<<(N_EDGES + 255) / 256, 256>>>(edst);
    k_scan1<<<NB_SCAN, SCAN_BLK>>>();
    k_scan2<<<1, 256>>>();
    k_addback<<<(N_NODES + 255) / 256, 256>>>();
    k_scatter<<<(N_EDGES + 255) / 256, 256>>>(esrc, edst, eval_);

    // fused layers: one warp per node, 8 warps/block
    int blocks = (N_NODES * 32 + 255) / 256;
    k_layer0<<<blocks, 256>>>(x, w1, ln1g, ln1b);
    k_layer1<<<blocks, 256>>>(w2, ln2g, ln2b, out);
}

// round 2
// speedup vs baseline: 1.1236x; 1.1236x over previous
#include <cuda_runtime.h>
#include <cuda_fp16.h>

#define N_NODES 100000
#define N_EDGES 1600000
#define D       128
#define LN_EPS  1e-5f

#define SCAN_BLK 512
#define NB_SCAN  ((N_NODES + SCAN_BLK - 1) / SCAN_BLK)   // 196

// ------- scratch (device globals; no allocation allowed) -------
__device__ int   g_rowptr[N_NODES + 1];
__device__ int   g_cursor[N_NODES];
__device__ int   g_partials[256];
__device__ int2  g_edge[N_EDGES];              // (src, __float_as_int(val))
__device__ __half g_xh[N_NODES * D];           // fp16 copy of x   (25.6 MB)
__device__ __half g_h[N_NODES * D];            // fp16 layer-0 out (25.6 MB)

// ---------------------------------------------------------------
// fp32 -> fp16 conversion of x (vectorized: 4 elems/thread)
// ---------------------------------------------------------------
__global__ void k_cvt(const float* __restrict__ in) {
    int i = blockIdx.x * blockDim.x + threadIdx.x;       // over N*D/4
    if (i >= N_NODES * D / 4) return;
    float4 v = ((const float4*)in)[i];
    __half2 lo = __floats2half2_rn(v.x, v.y);
    __half2 hi = __floats2half2_rn(v.z, v.w);
    uint2 packed;
    packed.x = *(unsigned int*)&lo;
    packed.y = *(unsigned int*)&hi;
    ((uint2*)g_xh)[i] = packed;
}

// ---------------------------------------------------------------
// CSR build
// ---------------------------------------------------------------
__global__ void k_zero() {
    int i = blockIdx.x * blockDim.x + threadIdx.x;
    int stride = gridDim.x * blockDim.x;
    for (int j = i; j <= N_NODES; j += stride) g_rowptr[j] = 0;
    for (int j = i; j <  N_NODES; j += stride) g_cursor[j] = 0;
}

__global__ void k_hist(const int* __restrict__ dst) {
    int e = blockIdx.x * blockDim.x + threadIdx.x;
    if (e < N_EDGES) atomicAdd(&g_rowptr[dst[e] + 1], 1);
}

__global__ void k_scan1() {
    __shared__ int sh[SCAN_BLK];
    int t = threadIdx.x;
    int i = blockIdx.x * SCAN_BLK + t;
    int v = (i < N_NODES) ? g_rowptr[i + 1] : 0;
    sh[t] = v;
    __syncthreads();
    #pragma unroll
    for (int off = 1; off < SCAN_BLK; off <<= 1) {
        int a = (t >= off) ? sh[t - off] : 0;
        __syncthreads();
        sh[t] += a;
        __syncthreads();
    }
    if (i < N_NODES) g_rowptr[i + 1] = sh[t];
    if (t == SCAN_BLK - 1) g_partials[blockIdx.x] = sh[t];
}

__global__ void k_scan2() {
    __shared__ int sh[256];
    int t = threadIdx.x;
    int v = (t < NB_SCAN) ? g_partials[t] : 0;
    sh[t] = v;
    __syncthreads();
    #pragma unroll
    for (int off = 1; off < 256; off <<= 1) {
        int a = (t >= off) ? sh[t - off] : 0;
        __syncthreads();
        sh[t] += a;
        __syncthreads();
    }
    if (t < NB_SCAN) g_partials[t] = sh[t] - v;  // exclusive
}

__global__ void k_addback() {
    int i = blockIdx.x * blockDim.x + threadIdx.x;
    if (i < N_NODES) g_rowptr[i + 1] += g_partials[i >> 9];
}

__global__ void k_scatter(const int* __restrict__ src,
                          const int* __restrict__ dst,
                          const float* __restrict__ val) {
    int e = blockIdx.x * blockDim.x + threadIdx.x;
    if (e >= N_EDGES) return;
    int d = dst[e];
    int p = g_rowptr[d] + atomicAdd(&g_cursor[d], 1);
    g_edge[p] = make_int2(src[e], __float_as_int(val[e]));
}

// ---------------------------------------------------------------
// fused gather(fp16)-aggregate(fp32) + diag-scale + LayerNorm (+ReLU)
// one warp per node; lane l owns features [4l, 4l+4)
// ---------------------------------------------------------------
__device__ __forceinline__ float4 acc_row(float4 acc, uint2 u, float v) {
    __half2 lo = *(__half2*)&u.x;
    __half2 hi = *(__half2*)&u.y;
    float2 flo = __half22float2(lo);
    float2 fhi = __half22float2(hi);
    acc.x = fmaf(v, flo.x, acc.x);
    acc.y = fmaf(v, flo.y, acc.y);
    acc.z = fmaf(v, fhi.x, acc.z);
    acc.w = fmaf(v, fhi.y, acc.w);
    return acc;
}

template <bool RELU, bool OUT_HALF>
__device__ __forceinline__ void agg_node(const __half* __restrict__ in,
                                         const float* __restrict__ w,
                                         const float* __restrict__ gam,
                                         const float* __restrict__ bet,
                                         void* __restrict__ out) {
    int warp = (blockIdx.x * blockDim.x + threadIdx.x) >> 5;
    int lane = threadIdx.x & 31;
    if (warp >= N_NODES) return;

    int beg = g_rowptr[warp];
    int end = g_rowptr[warp + 1];

    float4 acc = make_float4(0.f, 0.f, 0.f, 0.f);
    const uint2* in2 = (const uint2*)in;     // 4 halfs per lane-load, 32 per row

    int e = beg;
    for (; e + 4 <= end; e += 4) {
        int2 e0 = g_edge[e],     e1 = g_edge[e + 1];
        int2 e2 = g_edge[e + 2], e3 = g_edge[e + 3];
        uint2 x0 = in2[e0.x * 32 + lane];
        uint2 x1 = in2[e1.x * 32 + lane];
        uint2 x2 = in2[e2.x * 32 + lane];
        uint2 x3 = in2[e3.x * 32 + lane];
        acc = acc_row(acc, x0, __int_as_float(e0.y));
        acc = acc_row(acc, x1, __int_as_float(e1.y));
        acc = acc_row(acc, x2, __int_as_float(e2.y));
        acc = acc_row(acc, x3, __int_as_float(e3.y));
    }
    for (; e < end; e++) {
        int2 ed = g_edge[e];
        uint2 x0 = in2[ed.x * 32 + lane];
        acc = acc_row(acc, x0, __int_as_float(ed.y));
    }

    // diag transform: t = acc * w
    float4 w4 = ((const float4*)w)[lane];
    float4 t;
    t.x = acc.x * w4.x; t.y = acc.y * w4.y;
    t.z = acc.z * w4.z; t.w = acc.w * w4.w;

    // LayerNorm via warp reduce
    float s  = t.x + t.y + t.z + t.w;
    float sq = t.x * t.x + t.y * t.y + t.z * t.z + t.w * t.w;
    #pragma unroll
    for (int o = 16; o; o >>= 1) {
        s  += __shfl_xor_sync(0xffffffffu, s,  o);
        sq += __shfl_xor_sync(0xffffffffu, sq, o);
    }
    float mu  = s * (1.f / D);
    float var = sq * (1.f / D) - mu * mu;
    float rs  = rsqrtf(var + LN_EPS);

    float4 g4 = ((const float4*)gam)[lane];
    float4 b4 = ((const float4*)bet)[lane];
    float4 o4;
    o4.x = fmaf((t.x - mu) * rs, g4.x, b4.x);
    o4.y = fmaf((t.y - mu) * rs, g4.y, b4.y);
    o4.z = fmaf((t.z - mu) * rs, g4.z, b4.z);
    o4.w = fmaf((t.w - mu) * rs, g4.w, b4.w);
    if (RELU) {
        o4.x = fmaxf(o4.x, 0.f); o4.y = fmaxf(o4.y, 0.f);
        o4.z = fmaxf(o4.z, 0.f); o4.w = fmaxf(o4.w, 0.f);
    }

    if (OUT_HALF) {
        __half2 lo = __floats2half2_rn(o4.x, o4.y);
        __half2 hi = __floats2half2_rn(o4.z, o4.w);
        uint2 packed;
        packed.x = *(unsigned int*)&lo;
        packed.y = *(unsigned int*)&hi;
        ((uint2*)out)[warp * 32 + lane] = packed;
    } else {
        ((float4*)out)[warp * 32 + lane] = o4;
    }
}

__global__ void k_layer0(const float* __restrict__ w,
                         const float* __restrict__ gam,
                         const float* __restrict__ bet) {
    agg_node<true, true>(g_xh, w, gam, bet, (void*)g_h);
}

__global__ void k_layer1(const float* __restrict__ w,
                         const float* __restrict__ gam,
                         const float* __restrict__ bet,
                         float* __restrict__ out) {
    agg_node<false, false>(g_h, w, gam, bet, (void*)out);
}

// ---------------------------------------------------------------
extern "C" void kernel_launch(void* const* d_in, const int* in_sizes, int n_in,
                              void* d_out, int out_size) {
    const float* x     = (const float*)d_in[0];
    const int*   esrc  = (const int*)  d_in[1];
    const int*   edst  = (const int*)  d_in[2];
    const float* eval_ = (const float*)d_in[3];
    const float* w1    = (const float*)d_in[4];
    const float* w2    = (const float*)d_in[5];
    const float* ln1g  = (const float*)d_in[6];
    const float* ln1b  = (const float*)d_in[7];
    const float* ln2g  = (const float*)d_in[8];
    const float* ln2b  = (const float*)d_in[9];
    float* out = (float*)d_out;

    // x -> fp16 (overlaps CSR build on the same stream queue)
    k_cvt<<<(N_NODES * D / 4 + 255) / 256, 256>>>(x);

    // CSR build
    k_zero<<<256, 256>>>();
    k_hist<<<(N_EDGES + 255) / 256, 256>>>(edst);
    k_scan1<<<NB_SCAN, SCAN_BLK>>>();
    k_scan2<<<1, 256>>>();
    k_addback<<<(N_NODES + 255) / 256, 256>>>();
    k_scatter<<<(N_EDGES + 255) / 256, 256>>>(esrc, edst, eval_);

    // fused layers: one warp per node, 8 warps/block
    int blocks = (N_NODES * 32 + 255) / 256;
    k_layer0<<<blocks, 256>>>(w1, ln1g, ln1b);
    k_layer1<<<blocks, 256>>>(w2, ln2g, ln2b, out);
}